// round 7
// baseline (speedup 1.0000x reference)
#include <cuda_runtime.h>
#include <cuda_bf16.h>
#include <cstdint>

// Problem shape (fixed by the reference)
#define BB 8
#define CC 16
#define HH 512
#define WW 1024

// One thread handles 4 consecutive-w pixels of one (b,h) row.
// disp is shared across the 16 channels: compute x0/x1/weights once per pixel,
// then loop channels. Per channel iteration: 8 gather loads (L1-adjacent,
// streaming evict-first) and one aligned float4 streaming store.
// Round-5 evidence: occupancy is NOT the limiter (occ 46%->66% left DRAM% flat
// at ~68%); the plateau is mixed read+write stream efficiency, so this round
// adds .cs streaming hints on the once-touched input/output lines.
__global__ __launch_bounds__(256) void warp_disp_kernel(
    const float* __restrict__ input,   // [B,C,H,W]
    const float* __restrict__ disp,    // [B,1,H,W]
    float* __restrict__ out)           // [B,C,H,W]
{
    const int tid = blockIdx.x * blockDim.x + threadIdx.x;   // 1M threads
    const int w0  = (tid * 4) & (WW - 1);                    // 0..1020, step 4
    const int bh  = tid / (WW / 4);                          // b*H + h
    const int h   = bh & (HH - 1);
    const int b   = bh >> 9;                                 // /HH

    // disp layout [B,1,H,W] == [B*H*W]; aligned float4 load (streaming)
    const float4 d4 = __ldcs((const float4*)(disp + bh * WW + w0));

    int   x0[4], x1[4];
    float wl[4], wr[4];
    const float dvals[4] = {d4.x, d4.y, d4.z, d4.w};
    #pragma unroll
    for (int i = 0; i < 4; ++i) {
        float x = (float)(w0 + i) + dvals[i];
        x = fminf(fmaxf(x, 0.0f), (float)(WW - 1));
        const float x0f = floorf(x);
        const float x1f = fminf(x0f + 1.0f, (float)(WW - 1));
        x0[i] = (int)x0f;
        x1[i] = (int)x1f;
        wl[i] = x1f - x;          // note: NOT 1-wr; both 0 at the right clamp
        wr[i] = x - x0f;
    }

    // All element offsets fit in int32 (64M elements max).
    const int row_base = (b * CC * HH + h) * WW;
    const float* in_row = input + row_base;
    float*      out_row = out   + row_base + w0;
    const int cstride = HH * WW;   // 524288

    #pragma unroll 4
    for (int c = 0; c < CC; ++c) {
        const float* rc = in_row + c * cstride;
        // Issue all 8 gathers before the FMA chain so the loads batch in the
        // memory pipe (maximal MLP within the iteration).
        float pl0 = __ldcs(rc + x0[0]);
        float pr0 = __ldcs(rc + x1[0]);
        float pl1 = __ldcs(rc + x0[1]);
        float pr1 = __ldcs(rc + x1[1]);
        float pl2 = __ldcs(rc + x0[2]);
        float pr2 = __ldcs(rc + x1[2]);
        float pl3 = __ldcs(rc + x0[3]);
        float pr3 = __ldcs(rc + x1[3]);
        float4 r;
        r.x = wl[0] * pl0 + wr[0] * pr0;
        r.y = wl[1] * pl1 + wr[1] * pr1;
        r.z = wl[2] * pl2 + wr[2] * pr2;
        r.w = wl[3] * pl3 + wr[3] * pr3;
        __stcs((float4*)(out_row + c * cstride), r);
    }
}

extern "C" void kernel_launch(void* const* d_in, const int* in_sizes, int n_in,
                              void* d_out, int out_size) {
    const float* input = (const float*)d_in[0];
    const float* disp  = (const float*)d_in[1];
    float* out = (float*)d_out;

    const int n_threads = BB * HH * (WW / 4);   // 1,048,576
    const int threads = 256;
    warp_disp_kernel<<<n_threads / threads, threads>>>(input, disp, out);
}

// round 9
// speedup vs baseline: 1.0823x; 1.0823x over previous
#include <cuda_runtime.h>
#include <cuda_bf16.h>
#include <cstdint>

// Problem shape (fixed by the reference)
#define BB 8
#define CC 16
#define HH 512
#define WW 1024

// One block (256 threads) = one (b,h) row of 1024 pixels.
// Thread t handles pixels {t, t+256, t+512, t+768}: per-instruction the warp's
// 32 lanes touch ~32 CONSECUTIVE pixels (~128B ~= 1-2 L1 wavefronts) instead of
// the 512B/4-wavefront span of the consecutive-pixels-per-thread layout.
// Round-7 evidence: L1tex wavefront throughput (L1=67%) co-limits with DRAM
// (68%); this layout cuts gather wavefronts ~2.5x. Streaming (.cs) hints are
// REVERTED: round-7 showed they destroy the x0/x1 line reuse (DRAM 68->56%).
__global__ __launch_bounds__(256) void warp_disp_kernel(
    const float* __restrict__ input,   // [B,C,H,W]
    const float* __restrict__ disp,    // [B,1,H,W]
    float* __restrict__ out)           // [B,C,H,W]
{
    const int bh = blockIdx.x;            // b*H + h, 0..4095
    const int h  = bh & (HH - 1);
    const int b  = bh >> 9;               // /HH
    const int t  = threadIdx.x;

    const float* drow = disp + bh * WW;

    int   x0[4], x1[4];
    float wl[4], wr[4];
    #pragma unroll
    for (int j = 0; j < 4; ++j) {
        const int w = t + j * 256;
        const float d = __ldg(drow + w);          // coalesced
        float x = (float)w + d;
        x = fminf(fmaxf(x, 0.0f), (float)(WW - 1));
        const float x0f = floorf(x);
        const float x1f = fminf(x0f + 1.0f, (float)(WW - 1));
        x0[j] = (int)x0f;
        x1[j] = (int)x1f;
        wl[j] = x1f - x;          // note: NOT 1-wr; both 0 at the right clamp
        wr[j] = x - x0f;
    }

    // All element offsets fit in int32 (64M elements max).
    const int row_base = (b * CC * HH + h) * WW;
    const int cstride  = HH * WW;   // 524288

    #pragma unroll 4
    for (int c = 0; c < CC; ++c) {
        const float* rc = input + row_base + c * cstride;
        float*       oc = out   + row_base + c * cstride;
        // Batch all 8 gathers before the FMA/store chain (MLP within iter).
        const float pl0 = __ldg(rc + x0[0]);
        const float pr0 = __ldg(rc + x1[0]);
        const float pl1 = __ldg(rc + x0[1]);
        const float pr1 = __ldg(rc + x1[1]);
        const float pl2 = __ldg(rc + x0[2]);
        const float pr2 = __ldg(rc + x1[2]);
        const float pl3 = __ldg(rc + x0[3]);
        const float pr3 = __ldg(rc + x1[3]);
        oc[t +   0] = wl[0] * pl0 + wr[0] * pr0;  // coalesced STG.32
        oc[t + 256] = wl[1] * pl1 + wr[1] * pr1;
        oc[t + 512] = wl[2] * pl2 + wr[2] * pr2;
        oc[t + 768] = wl[3] * pl3 + wr[3] * pr3;
    }
}

extern "C" void kernel_launch(void* const* d_in, const int* in_sizes, int n_in,
                              void* d_out, int out_size) {
    const float* input = (const float*)d_in[0];
    const float* disp  = (const float*)d_in[1];
    float* out = (float*)d_out;

    warp_disp_kernel<<<BB * HH, 256>>>(input, disp, out);   // 4096 blocks
}